// round 13
// baseline (speedup 1.0000x reference)
#include <cuda_runtime.h>
#include <cuda_bf16.h>
#include <math.h>
#include <stdint.h>

#define B_    2
#define S_    2048
#define DIN_  2048
#define H_    32
#define KVH_  8
#define HD_   64
#define MROWS (B_ * S_)          // 4096
#define LOG2E 1.44269504f
#define GK    2048
#define KVELEM ((size_t)MROWS * KVH_ * HD_)   // 2,097,152

// ---------------- scratch (static device arrays; no allocation) ------------
__device__ float g_q[(size_t)MROWS * H_   * HD_];
__device__ float g_k[KVELEM];
__device__ float g_v[KVELEM];
__device__ float g_o[(size_t)MROWS * H_   * HD_];
__device__ __nv_bfloat16 g_khi[KVELEM];
__device__ __nv_bfloat16 g_klo[KVELEM];
__device__ __nv_bfloat16 g_vhi[KVELEM];
__device__ __nv_bfloat16 g_vlo[KVELEM];

// ---------------------------------------------------------------------------
// helpers
// ---------------------------------------------------------------------------
__device__ __forceinline__ float to_tf32(float x) {
    float y;
    asm("cvt.rna.tf32.f32 %0, %1;" : "=f"(y) : "f"(x));
    return y;
}
__device__ __forceinline__ void mma_tf32(float c[4],
                                         const uint32_t a[4],
                                         uint32_t b0, uint32_t b1) {
    asm volatile(
        "mma.sync.aligned.m16n8k8.row.col.f32.tf32.tf32.f32 "
        "{%0,%1,%2,%3}, {%4,%5,%6,%7}, {%8,%9}, {%0,%1,%2,%3};"
        : "+f"(c[0]), "+f"(c[1]), "+f"(c[2]), "+f"(c[3])
        : "r"(a[0]), "r"(a[1]), "r"(a[2]), "r"(a[3]), "r"(b0), "r"(b1));
}
__device__ __forceinline__ void ldm4(uint32_t r[4], uint32_t addr) {
    asm volatile(
        "ldmatrix.sync.aligned.m8n8.x4.shared.b16 {%0,%1,%2,%3}, [%4];"
        : "=r"(r[0]), "=r"(r[1]), "=r"(r[2]), "=r"(r[3]) : "r"(addr));
}
__device__ __forceinline__ uint32_t smem_u32(const void* p) {
    return (uint32_t)__cvta_generic_to_shared(p);
}
__device__ __forceinline__ uint32_t packbf(float x0, float x1) {
    uint32_t r;
    asm("cvt.rn.bf16x2.f32 %0, %1, %2;" : "=r"(r) : "f"(x1), "f"(x0));
    return r;
}
__device__ __forceinline__ void splitpack(float x0, float x1,
                                          uint32_t& hi, uint32_t& lo) {
    hi = packbf(x0, x1);
    __nv_bfloat162 hb = *(__nv_bfloat162*)&hi;
    lo = packbf(x0 - __bfloat162float(hb.x), x1 - __bfloat162float(hb.y));
}
__device__ __forceinline__ void mma_bf16(float c[4],
                                         const uint32_t a[4],
                                         uint32_t b0, uint32_t b1) {
    asm volatile(
        "mma.sync.aligned.m16n8k16.row.col.f32.bf16.bf16.f32 "
        "{%0,%1,%2,%3}, {%4,%5,%6,%7}, {%8,%9}, {%0,%1,%2,%3};"
        : "+f"(c[0]), "+f"(c[1]), "+f"(c[2]), "+f"(c[3])
        : "r"(a[0]), "r"(a[1]), "r"(a[2]), "r"(a[3]), "r"(b0), "r"(b1));
}
__device__ __forceinline__ void ldm4t(uint32_t r[4], uint32_t addr) {
    asm volatile(
        "ldmatrix.sync.aligned.m8n8.x4.trans.shared.b16 {%0,%1,%2,%3}, [%4];"
        : "=r"(r[0]), "=r"(r[1]), "=r"(r[2]), "=r"(r[3]) : "r"(addr));
}

// ---------------------------------------------------------------------------
// tf32 GEMM via mma.sync + ldmatrix (validated R10)
// ---------------------------------------------------------------------------
#define AST   36
#define BUFSZ (128 * AST)

__device__ __forceinline__ void gemm_tf32_body(const float* __restrict__ A,
                                               const float* __restrict__ W,
                                               float* __restrict__ C,
                                               int N, int bm, int bn) {
    extern __shared__ float sm[];
    float* AsBase = sm;
    float* WsBase = sm + 2 * BUFSZ;

    const int tid  = threadIdx.x;
    const int lane = tid & 31;
    const int warp = tid >> 5;
    const int gid  = lane >> 2;
    const int tig  = lane & 3;

    const int rb = (warp & 1) * 64;
    const int nb = (warp >> 1) * 32;

    const int lrow = tid >> 1;
    const int col0 = (tid & 1) * 16;
    const float* pA = A + (size_t)(bm + lrow) * GK + col0;
    const float* pW = W + (size_t)(bn + lrow) * GK + col0;

    const int g    = lane >> 3;
    const int grow = lane & 7;
    int a_off[4], b_off[2];
#pragma unroll
    for (int i = 0; i < 4; i++)
        a_off[i] = (rb + i * 16 + (g & 1) * 8 + grow) * AST + (g >> 1) * 4;
#pragma unroll
    for (int jj = 0; jj < 2; jj++)
        b_off[jj] = (nb + (jj * 2 + (g >> 1)) * 8 + grow) * AST + (g & 1) * 4;

    const uint32_t a_smem = smem_u32(AsBase);
    const uint32_t w_smem = smem_u32(WsBase);

    float c[4][4][4];
#pragma unroll
    for (int i = 0; i < 4; i++)
#pragma unroll
        for (int j = 0; j < 4; j++)
#pragma unroll
            for (int r = 0; r < 4; r++) c[i][j][r] = 0.f;

    float4 pa[4], pw[4];
#pragma unroll
    for (int i = 0; i < 4; i++) {
        pa[i] = *(const float4*)(pA + i * 4);
        pw[i] = *(const float4*)(pW + i * 4);
    }

    int buf = 0;
    for (int k0 = 0; k0 < GK; k0 += 32) {
        float* dA = AsBase + buf * BUFSZ + lrow * AST + col0;
        float* dW = WsBase + buf * BUFSZ + lrow * AST + col0;
#pragma unroll
        for (int i = 0; i < 4; i++) {
            *(float4*)(dA + i * 4) = make_float4(to_tf32(pa[i].x), to_tf32(pa[i].y),
                                                 to_tf32(pa[i].z), to_tf32(pa[i].w));
            *(float4*)(dW + i * 4) = make_float4(to_tf32(pw[i].x), to_tf32(pw[i].y),
                                                 to_tf32(pw[i].z), to_tf32(pw[i].w));
        }
        __syncthreads();

        if (k0 + 32 < GK) {
#pragma unroll
            for (int i = 0; i < 4; i++) {
                pa[i] = *(const float4*)(pA + k0 + 32 + i * 4);
                pw[i] = *(const float4*)(pW + k0 + 32 + i * 4);
            }
        }

        const uint32_t ab = a_smem + buf * (BUFSZ * 4);
        const uint32_t wb = w_smem + buf * (BUFSZ * 4);
#pragma unroll
        for (int kk = 0; kk < 32; kk += 8) {
            uint32_t af[4][4];
#pragma unroll
            for (int i = 0; i < 4; i++) ldm4(af[i], ab + 4 * (a_off[i] + kk));
            uint32_t bq[2][4];
#pragma unroll
            for (int jj = 0; jj < 2; jj++) ldm4(bq[jj], wb + 4 * (b_off[jj] + kk));
#pragma unroll
            for (int i = 0; i < 4; i++)
#pragma unroll
                for (int j = 0; j < 4; j++)
                    mma_tf32(c[i][j], af[i],
                             bq[j >> 1][(j & 1) * 2], bq[j >> 1][(j & 1) * 2 + 1]);
        }
        buf ^= 1;
    }

#pragma unroll
    for (int i = 0; i < 4; i++) {
#pragma unroll
        for (int j = 0; j < 4; j++) {
            const int orow = bm + rb + i * 16 + gid;
            const int ocol = bn + nb + j * 8 + tig * 2;
            *(float2*)(C + (size_t)orow * N + ocol)       = make_float2(c[i][j][0], c[i][j][1]);
            *(float2*)(C + (size_t)(orow + 8) * N + ocol) = make_float2(c[i][j][2], c[i][j][3]);
        }
    }
}

#define GSMEM (4 * BUFSZ * 4)

__global__ void __launch_bounds__(256) gemm_tf32(const float* __restrict__ A,
                                                 const float* __restrict__ W,
                                                 float* __restrict__ C, int N) {
    gemm_tf32_body(A, W, C, N, blockIdx.y * 128, blockIdx.x * 128);
}

__global__ void __launch_bounds__(256) gemm_tf32_kv(const float* __restrict__ A,
                                                    const float* __restrict__ Wk,
                                                    const float* __restrict__ Wv,
                                                    float* __restrict__ Ck,
                                                    float* __restrict__ Cv, int N) {
    const float* W = (blockIdx.z == 0) ? Wk : Wv;
    float*       C = (blockIdx.z == 0) ? Ck : Cv;
    gemm_tf32_body(A, W, C, N, blockIdx.y * 128, blockIdx.x * 128);
}

// ---------------------------------------------------------------------------
// Fused per-head RMSNorm + RoPE (validated)
// ---------------------------------------------------------------------------
__global__ void __launch_bounds__(256) norm_rope(float* __restrict__ t,
                                                 const float* __restrict__ w,
                                                 const float* __restrict__ cosT,
                                                 const float* __restrict__ sinT,
                                                 int heads, int nrows) {
    const int warp = blockIdx.x * (blockDim.x >> 5) + (threadIdx.x >> 5);
    if (warp >= nrows) return;
    const int lane = threadIdx.x & 31;
    const int s = (warp / heads) % S_;

    float* row = t + (size_t)warp * HD_;
    float a = row[lane];
    float b = row[lane + 32];

    float ss = a * a + b * b;
#pragma unroll
    for (int o = 16; o > 0; o >>= 1) ss += __shfl_xor_sync(0xffffffffu, ss, o);

    const float r = rsqrtf(ss * (1.0f / 64.0f) + 1e-6f);
    const float n0 = a * r * w[lane];
    const float n1 = b * r * w[lane + 32];

    const float c0 = cosT[s * HD_ + lane];
    const float s0 = sinT[s * HD_ + lane];
    const float c1 = cosT[s * HD_ + lane + 32];
    const float s1 = sinT[s * HD_ + lane + 32];

    row[lane]      = n0 * c0 - n1 * s0;
    row[lane + 32] = n1 * c1 + n0 * s1;
}

// ---------------------------------------------------------------------------
// One-shot K/V split-bf16 conversion (numerics identical to in-loop splitpack)
// ---------------------------------------------------------------------------
__global__ void __launch_bounds__(256) convert_kv(const float* __restrict__ k,
                                                  const float* __restrict__ v,
                                                  __nv_bfloat16* __restrict__ khi,
                                                  __nv_bfloat16* __restrict__ klo,
                                                  __nv_bfloat16* __restrict__ vhi,
                                                  __nv_bfloat16* __restrict__ vlo) {
    const int i = blockIdx.x * blockDim.x + threadIdx.x;   // one float4 each
    if (i >= (int)(KVELEM / 4)) return;
    float4 kk = ((const float4*)k)[i];
    float4 vv = ((const float4*)v)[i];
    uint32_t h0, h1, l0, l1;
    splitpack(kk.x, kk.y, h0, l0);
    splitpack(kk.z, kk.w, h1, l1);
    ((uint2*)khi)[i] = make_uint2(h0, h1);
    ((uint2*)klo)[i] = make_uint2(l0, l1);
    splitpack(vv.x, vv.y, h0, l0);
    splitpack(vv.z, vv.w, h1, l1);
    ((uint2*)vhi)[i] = make_uint2(h0, h1);
    ((uint2*)vlo)[i] = make_uint2(l0, l1);
}

// ---------------------------------------------------------------------------
// Tensor-core causal flash attention, split-bf16, pre-converted K/V.
// CTA: 128 q rows (8 warps), key tiles of 32. Grid (S/128, H, B).
// ---------------------------------------------------------------------------
#define KVST 72

__global__ void __launch_bounds__(256) attn_tc(const float* __restrict__ q,
                                               const __nv_bfloat16* __restrict__ khi,
                                               const __nv_bfloat16* __restrict__ klo,
                                               const __nv_bfloat16* __restrict__ vhi,
                                               const __nv_bfloat16* __restrict__ vlo,
                                               float* __restrict__ o) {
    __shared__ unsigned short ksh_hi[32][KVST], ksh_lo[32][KVST];
    __shared__ unsigned short vsh_hi[32][KVST], vsh_lo[32][KVST];

    const int t    = threadIdx.x;
    const int lane = t & 31;
    const int w    = t >> 5;              // 0..7
    const int gid  = lane >> 2;
    const int tig  = lane & 3;
    const int b    = blockIdx.z;
    const int h    = blockIdx.y;
    const int kh   = h >> 2;
    const int qb   = blockIdx.x * 128;
    const int r0   = qb + w * 16 + gid;

    uint32_t qh[4][4], ql[4][4];
    {
        const float* q0 = q + ((size_t)(b * S_ + r0) * H_ + h) * HD_;
        const float* q1 = q0 + (size_t)8 * H_ * HD_;
#pragma unroll
        for (int kc = 0; kc < 4; kc++) {
            const int d0 = kc * 16 + tig * 2;
            float2 x00 = *(const float2*)(q0 + d0);
            float2 x10 = *(const float2*)(q1 + d0);
            float2 x02 = *(const float2*)(q0 + d0 + 8);
            float2 x12 = *(const float2*)(q1 + d0 + 8);
            splitpack(x00.x * 0.125f, x00.y * 0.125f, qh[kc][0], ql[kc][0]);
            splitpack(x10.x * 0.125f, x10.y * 0.125f, qh[kc][1], ql[kc][1]);
            splitpack(x02.x * 0.125f, x02.y * 0.125f, qh[kc][2], ql[kc][2]);
            splitpack(x12.x * 0.125f, x12.y * 0.125f, qh[kc][3], ql[kc][3]);
        }
    }

    float oc[8][4];
#pragma unroll
    for (int nt = 0; nt < 8; nt++)
#pragma unroll
        for (int r = 0; r < 4; r++) oc[nt][r] = 0.f;
    float m0 = -1e30f, m1 = -1e30f, l0 = 0.f, l1 = 0.f;

    const uint32_t vhi_base = smem_u32(&vsh_hi[0][0]);
    const uint32_t vlo_base = smem_u32(&vsh_lo[0][0]);
    const int lm_key = lane & 15;
    const int lm_d   = (lane >> 4) * 8;

    // loader mapping: 256 threads cover 32 keys x 8 uint4 (64 bf16) exactly
    const int lkey = t >> 3;
    const int lc   = t & 7;

    for (int n0 = 0; n0 < qb + 128; n0 += 32) {
        {
            const size_t gb = ((size_t)(b * S_ + n0 + lkey) * KVH_ + kh) * HD_ + lc * 8;
            *(uint4*)&ksh_hi[lkey][lc * 8] = *(const uint4*)(khi + gb);
            *(uint4*)&ksh_lo[lkey][lc * 8] = *(const uint4*)(klo + gb);
            *(uint4*)&vsh_hi[lkey][lc * 8] = *(const uint4*)(vhi + gb);
            *(uint4*)&vsh_lo[lkey][lc * 8] = *(const uint4*)(vlo + gb);
        }
        __syncthreads();

        const bool active = (n0 <= qb + w * 16 + 15);   // warp-uniform
        if (active) {
            float sc[4][4];
#pragma unroll
            for (int j = 0; j < 4; j++)
#pragma unroll
                for (int r = 0; r < 4; r++) sc[j][r] = 0.f;

#pragma unroll
            for (int j = 0; j < 4; j++) {
                const int key = j * 8 + gid;
#pragma unroll
                for (int kc = 0; kc < 4; kc++) {
                    const int d = kc * 16 + tig * 2;
                    uint32_t bh0 = *(const uint32_t*)&ksh_hi[key][d];
                    uint32_t bh1 = *(const uint32_t*)&ksh_hi[key][d + 8];
                    uint32_t bl0 = *(const uint32_t*)&ksh_lo[key][d];
                    uint32_t bl1 = *(const uint32_t*)&ksh_lo[key][d + 8];
                    mma_bf16(sc[j], qh[kc], bh0, bh1);
                    mma_bf16(sc[j], qh[kc], bl0, bl1);
                    mma_bf16(sc[j], ql[kc], bh0, bh1);
                }
            }

            if (n0 + 31 > qb + w * 16) {
#pragma unroll
                for (int j = 0; j < 4; j++) {
                    const int col = n0 + j * 8 + tig * 2;
                    if (col     > r0)     sc[j][0] = -1e30f;
                    if (col + 1 > r0)     sc[j][1] = -1e30f;
                    if (col     > r0 + 8) sc[j][2] = -1e30f;
                    if (col + 1 > r0 + 8) sc[j][3] = -1e30f;
                }
            }

            float tm0 = -1e30f, tm1 = -1e30f;
#pragma unroll
            for (int j = 0; j < 4; j++) {
                tm0 = fmaxf(tm0, fmaxf(sc[j][0], sc[j][1]));
                tm1 = fmaxf(tm1, fmaxf(sc[j][2], sc[j][3]));
            }
            tm0 = fmaxf(tm0, __shfl_xor_sync(0xffffffffu, tm0, 1));
            tm0 = fmaxf(tm0, __shfl_xor_sync(0xffffffffu, tm0, 2));
            tm1 = fmaxf(tm1, __shfl_xor_sync(0xffffffffu, tm1, 1));
            tm1 = fmaxf(tm1, __shfl_xor_sync(0xffffffffu, tm1, 2));

            const float mn0 = fmaxf(m0, tm0);
            const float mn1 = fmaxf(m1, tm1);
            const float al0 = exp2f((m0 - mn0) * LOG2E);
            const float al1 = exp2f((m1 - mn1) * LOG2E);
            m0 = mn0;  m1 = mn1;
            l0 *= al0; l1 *= al1;
#pragma unroll
            for (int nt = 0; nt < 8; nt++) {
                oc[nt][0] *= al0; oc[nt][1] *= al0;
                oc[nt][2] *= al1; oc[nt][3] *= al1;
            }
#pragma unroll
            for (int j = 0; j < 4; j++) {
                sc[j][0] = exp2f((sc[j][0] - mn0) * LOG2E);
                sc[j][1] = exp2f((sc[j][1] - mn0) * LOG2E);
                sc[j][2] = exp2f((sc[j][2] - mn1) * LOG2E);
                sc[j][3] = exp2f((sc[j][3] - mn1) * LOG2E);
                l0 += sc[j][0] + sc[j][1];
                l1 += sc[j][2] + sc[j][3];
            }

#pragma unroll
            for (int kc2 = 0; kc2 < 2; kc2++) {
                uint32_t pah[4], pal[4];
                splitpack(sc[2 * kc2][0],     sc[2 * kc2][1],     pah[0], pal[0]);
                splitpack(sc[2 * kc2][2],     sc[2 * kc2][3],     pah[1], pal[1]);
                splitpack(sc[2 * kc2 + 1][0], sc[2 * kc2 + 1][1], pah[2], pal[2]);
                splitpack(sc[2 * kc2 + 1][2], sc[2 * kc2 + 1][3], pah[3], pal[3]);
#pragma unroll
                for (int ntp = 0; ntp < 4; ntp++) {
                    const uint32_t off =
                        (uint32_t)(((kc2 * 16 + lm_key) * KVST + ntp * 16 + lm_d) * 2);
                    uint32_t vh[4], vl[4];
                    ldm4t(vh, vhi_base + off);
                    ldm4t(vl, vlo_base + off);
                    mma_bf16(oc[2 * ntp],     pah, vh[0], vh[1]);
                    mma_bf16(oc[2 * ntp],     pah, vl[0], vl[1]);
                    mma_bf16(oc[2 * ntp],     pal, vh[0], vh[1]);
                    mma_bf16(oc[2 * ntp + 1], pah, vh[2], vh[3]);
                    mma_bf16(oc[2 * ntp + 1], pah, vl[2], vl[3]);
                    mma_bf16(oc[2 * ntp + 1], pal, vh[2], vh[3]);
                }
            }
        }
        __syncthreads();
    }

    l0 += __shfl_xor_sync(0xffffffffu, l0, 1);
    l0 += __shfl_xor_sync(0xffffffffu, l0, 2);
    l1 += __shfl_xor_sync(0xffffffffu, l1, 1);
    l1 += __shfl_xor_sync(0xffffffffu, l1, 2);
    const float inv0 = 1.f / l0;
    const float inv1 = 1.f / l1;

    float* o0 = o + ((size_t)(b * S_ + r0) * H_ + h) * HD_;
    float* o1 = o0 + (size_t)8 * H_ * HD_;
#pragma unroll
    for (int nt = 0; nt < 8; nt++) {
        *(float2*)(o0 + nt * 8 + tig * 2) =
            make_float2(oc[nt][0] * inv0, oc[nt][1] * inv0);
        *(float2*)(o1 + nt * 8 + tig * 2) =
            make_float2(oc[nt][2] * inv1, oc[nt][3] * inv1);
    }
}

// ---------------------------------------------------------------------------
extern "C" void kernel_launch(void* const* d_in, const int* in_sizes, int n_in,
                              void* d_out, int out_size) {
    const float* x     = (const float*)d_in[0];
    // d_in[1] = mask (unused; causal hardcoded)
    const float* cosT  = (const float*)d_in[2];
    const float* sinT  = (const float*)d_in[3];
    const float* Wq    = (const float*)d_in[4];
    const float* Wk    = (const float*)d_in[5];
    const float* Wv    = (const float*)d_in[6];
    const float* Wo    = (const float*)d_in[7];
    const float* wqn   = (const float*)d_in[8];
    const float* wkn   = (const float*)d_in[9];
    float* out = (float*)d_out;

    float *q, *k, *v, *o;
    __nv_bfloat16 *khi, *klo, *vhi, *vlo;
    cudaGetSymbolAddress((void**)&q, g_q);
    cudaGetSymbolAddress((void**)&k, g_k);
    cudaGetSymbolAddress((void**)&v, g_v);
    cudaGetSymbolAddress((void**)&o, g_o);
    cudaGetSymbolAddress((void**)&khi, g_khi);
    cudaGetSymbolAddress((void**)&klo, g_klo);
    cudaGetSymbolAddress((void**)&vhi, g_vhi);
    cudaGetSymbolAddress((void**)&vlo, g_vlo);

    cudaFuncSetAttribute(gemm_tf32,    cudaFuncAttributeMaxDynamicSharedMemorySize, GSMEM);
    cudaFuncSetAttribute(gemm_tf32_kv, cudaFuncAttributeMaxDynamicSharedMemorySize, GSMEM);

    // projections
    gemm_tf32<<<dim3((H_ * HD_) / 128, MROWS / 128), 256, GSMEM>>>(x, Wq, q, H_ * HD_);
    gemm_tf32_kv<<<dim3((KVH_ * HD_) / 128, MROWS / 128, 2), 256, GSMEM>>>(x, Wk, Wv, k, v,
                                                                           KVH_ * HD_);

    // fused RMSNorm + RoPE on q and k
    {
        const int qrows = MROWS * H_;
        const int krows = MROWS * KVH_;
        norm_rope<<<(qrows + 7) / 8, 256>>>(q, wqn, cosT, sinT, H_, qrows);
        norm_rope<<<(krows + 7) / 8, 256>>>(k, wkn, cosT, sinT, KVH_, krows);
    }

    // one-shot K/V split-bf16 conversion
    convert_kv<<<(int)(KVELEM / 4 + 255) / 256, 256>>>(k, v, khi, klo, vhi, vlo);

    // causal GQA attention (split-bf16 tensor cores, pre-converted K/V)
    attn_tc<<<dim3(S_ / 128, H_, B_), 256>>>(q, khi, klo, vhi, vlo, o);

    // output projection
    gemm_tf32<<<dim3(DIN_ / 128, MROWS / 128), 256, GSMEM>>>(o, Wo, out, DIN_);
}

// round 14
// speedup vs baseline: 1.5436x; 1.5436x over previous
#include <cuda_runtime.h>
#include <cuda_bf16.h>
#include <math.h>
#include <stdint.h>

#define B_    2
#define S_    2048
#define DIN_  2048
#define H_    32
#define KVH_  8
#define HD_   64
#define MROWS (B_ * S_)          // 4096
#define LOG2E 1.44269504f
#define GK    2048
#define KVELEM ((size_t)MROWS * KVH_ * HD_)   // 2,097,152

// ---------------- scratch (static device arrays; no allocation) ------------
__device__ float g_q[(size_t)MROWS * H_   * HD_];
__device__ float g_k[KVELEM];
__device__ float g_v[KVELEM];
__device__ float g_o[(size_t)MROWS * H_   * HD_];
__device__ __nv_bfloat16 g_khi[KVELEM];
__device__ __nv_bfloat16 g_klo[KVELEM];
__device__ __nv_bfloat16 g_vhi[KVELEM];
__device__ __nv_bfloat16 g_vlo[KVELEM];

// ---------------------------------------------------------------------------
// helpers
// ---------------------------------------------------------------------------
__device__ __forceinline__ float to_tf32(float x) {
    float y;
    asm("cvt.rna.tf32.f32 %0, %1;" : "=f"(y) : "f"(x));
    return y;
}
__device__ __forceinline__ void mma_tf32(float c[4],
                                         const uint32_t a[4],
                                         uint32_t b0, uint32_t b1) {
    asm volatile(
        "mma.sync.aligned.m16n8k8.row.col.f32.tf32.tf32.f32 "
        "{%0,%1,%2,%3}, {%4,%5,%6,%7}, {%8,%9}, {%0,%1,%2,%3};"
        : "+f"(c[0]), "+f"(c[1]), "+f"(c[2]), "+f"(c[3])
        : "r"(a[0]), "r"(a[1]), "r"(a[2]), "r"(a[3]), "r"(b0), "r"(b1));
}
__device__ __forceinline__ void ldm4(uint32_t r[4], uint32_t addr) {
    asm volatile(
        "ldmatrix.sync.aligned.m8n8.x4.shared.b16 {%0,%1,%2,%3}, [%4];"
        : "=r"(r[0]), "=r"(r[1]), "=r"(r[2]), "=r"(r[3]) : "r"(addr));
}
__device__ __forceinline__ uint32_t smem_u32(const void* p) {
    return (uint32_t)__cvta_generic_to_shared(p);
}
__device__ __forceinline__ uint32_t packbf(float x0, float x1) {
    uint32_t r;
    asm("cvt.rn.bf16x2.f32 %0, %1, %2;" : "=r"(r) : "f"(x1), "f"(x0));
    return r;
}
__device__ __forceinline__ void splitpack(float x0, float x1,
                                          uint32_t& hi, uint32_t& lo) {
    hi = packbf(x0, x1);
    __nv_bfloat162 hb = *(__nv_bfloat162*)&hi;
    lo = packbf(x0 - __bfloat162float(hb.x), x1 - __bfloat162float(hb.y));
}
__device__ __forceinline__ void mma_bf16(float c[4],
                                         const uint32_t a[4],
                                         uint32_t b0, uint32_t b1) {
    asm volatile(
        "mma.sync.aligned.m16n8k16.row.col.f32.bf16.bf16.f32 "
        "{%0,%1,%2,%3}, {%4,%5,%6,%7}, {%8,%9}, {%0,%1,%2,%3};"
        : "+f"(c[0]), "+f"(c[1]), "+f"(c[2]), "+f"(c[3])
        : "r"(a[0]), "r"(a[1]), "r"(a[2]), "r"(a[3]), "r"(b0), "r"(b1));
}
__device__ __forceinline__ void ldm4t(uint32_t r[4], uint32_t addr) {
    asm volatile(
        "ldmatrix.sync.aligned.m8n8.x4.trans.shared.b16 {%0,%1,%2,%3}, [%4];"
        : "=r"(r[0]), "=r"(r[1]), "=r"(r[2]), "=r"(r[3]) : "r"(addr));
}

// ---------------------------------------------------------------------------
// tf32 GEMM via mma.sync + ldmatrix (validated R10/R11)
// ---------------------------------------------------------------------------
#define AST   36
#define BUFSZ (128 * AST)

__device__ __forceinline__ void gemm_tf32_body(const float* __restrict__ A,
                                               const float* __restrict__ W,
                                               float* __restrict__ C,
                                               int N, int bm, int bn) {
    extern __shared__ float sm[];
    float* AsBase = sm;
    float* WsBase = sm + 2 * BUFSZ;

    const int tid  = threadIdx.x;
    const int lane = tid & 31;
    const int warp = tid >> 5;
    const int gid  = lane >> 2;
    const int tig  = lane & 3;

    const int rb = (warp & 1) * 64;
    const int nb = (warp >> 1) * 32;

    const int lrow = tid >> 1;
    const int col0 = (tid & 1) * 16;
    const float* pA = A + (size_t)(bm + lrow) * GK + col0;
    const float* pW = W + (size_t)(bn + lrow) * GK + col0;

    const int g    = lane >> 3;
    const int grow = lane & 7;
    int a_off[4], b_off[2];
#pragma unroll
    for (int i = 0; i < 4; i++)
        a_off[i] = (rb + i * 16 + (g & 1) * 8 + grow) * AST + (g >> 1) * 4;
#pragma unroll
    for (int jj = 0; jj < 2; jj++)
        b_off[jj] = (nb + (jj * 2 + (g >> 1)) * 8 + grow) * AST + (g & 1) * 4;

    const uint32_t a_smem = smem_u32(AsBase);
    const uint32_t w_smem = smem_u32(WsBase);

    float c[4][4][4];
#pragma unroll
    for (int i = 0; i < 4; i++)
#pragma unroll
        for (int j = 0; j < 4; j++)
#pragma unroll
            for (int r = 0; r < 4; r++) c[i][j][r] = 0.f;

    float4 pa[4], pw[4];
#pragma unroll
    for (int i = 0; i < 4; i++) {
        pa[i] = *(const float4*)(pA + i * 4);
        pw[i] = *(const float4*)(pW + i * 4);
    }

    int buf = 0;
    for (int k0 = 0; k0 < GK; k0 += 32) {
        float* dA = AsBase + buf * BUFSZ + lrow * AST + col0;
        float* dW = WsBase + buf * BUFSZ + lrow * AST + col0;
#pragma unroll
        for (int i = 0; i < 4; i++) {
            *(float4*)(dA + i * 4) = make_float4(to_tf32(pa[i].x), to_tf32(pa[i].y),
                                                 to_tf32(pa[i].z), to_tf32(pa[i].w));
            *(float4*)(dW + i * 4) = make_float4(to_tf32(pw[i].x), to_tf32(pw[i].y),
                                                 to_tf32(pw[i].z), to_tf32(pw[i].w));
        }
        __syncthreads();

        if (k0 + 32 < GK) {
#pragma unroll
            for (int i = 0; i < 4; i++) {
                pa[i] = *(const float4*)(pA + k0 + 32 + i * 4);
                pw[i] = *(const float4*)(pW + k0 + 32 + i * 4);
            }
        }

        const uint32_t ab = a_smem + buf * (BUFSZ * 4);
        const uint32_t wb = w_smem + buf * (BUFSZ * 4);
#pragma unroll
        for (int kk = 0; kk < 32; kk += 8) {
            uint32_t af[4][4];
#pragma unroll
            for (int i = 0; i < 4; i++) ldm4(af[i], ab + 4 * (a_off[i] + kk));
            uint32_t bq[2][4];
#pragma unroll
            for (int jj = 0; jj < 2; jj++) ldm4(bq[jj], wb + 4 * (b_off[jj] + kk));
#pragma unroll
            for (int i = 0; i < 4; i++)
#pragma unroll
                for (int j = 0; j < 4; j++)
                    mma_tf32(c[i][j], af[i],
                             bq[j >> 1][(j & 1) * 2], bq[j >> 1][(j & 1) * 2 + 1]);
        }
        buf ^= 1;
    }

#pragma unroll
    for (int i = 0; i < 4; i++) {
#pragma unroll
        for (int j = 0; j < 4; j++) {
            const int orow = bm + rb + i * 16 + gid;
            const int ocol = bn + nb + j * 8 + tig * 2;
            *(float2*)(C + (size_t)orow * N + ocol)       = make_float2(c[i][j][0], c[i][j][1]);
            *(float2*)(C + (size_t)(orow + 8) * N + ocol) = make_float2(c[i][j][2], c[i][j][3]);
        }
    }
}

#define GSMEM (4 * BUFSZ * 4)

__global__ void __launch_bounds__(256) gemm_tf32(const float* __restrict__ A,
                                                 const float* __restrict__ W,
                                                 float* __restrict__ C, int N) {
    gemm_tf32_body(A, W, C, N, blockIdx.y * 128, blockIdx.x * 128);
}

__global__ void __launch_bounds__(256) gemm_tf32_kv(const float* __restrict__ A,
                                                    const float* __restrict__ Wk,
                                                    const float* __restrict__ Wv,
                                                    float* __restrict__ Ck,
                                                    float* __restrict__ Cv, int N) {
    const float* W = (blockIdx.z == 0) ? Wk : Wv;
    float*       C = (blockIdx.z == 0) ? Ck : Cv;
    gemm_tf32_body(A, W, C, N, blockIdx.y * 128, blockIdx.x * 128);
}

// ---------------------------------------------------------------------------
// Fused per-head RMSNorm + RoPE (validated)
// ---------------------------------------------------------------------------
__global__ void __launch_bounds__(256) norm_rope(float* __restrict__ t,
                                                 const float* __restrict__ w,
                                                 const float* __restrict__ cosT,
                                                 const float* __restrict__ sinT,
                                                 int heads, int nrows) {
    const int warp = blockIdx.x * (blockDim.x >> 5) + (threadIdx.x >> 5);
    if (warp >= nrows) return;
    const int lane = threadIdx.x & 31;
    const int s = (warp / heads) % S_;

    float* row = t + (size_t)warp * HD_;
    float a = row[lane];
    float b = row[lane + 32];

    float ss = a * a + b * b;
#pragma unroll
    for (int o = 16; o > 0; o >>= 1) ss += __shfl_xor_sync(0xffffffffu, ss, o);

    const float r = rsqrtf(ss * (1.0f / 64.0f) + 1e-6f);
    const float n0 = a * r * w[lane];
    const float n1 = b * r * w[lane + 32];

    const float c0 = cosT[s * HD_ + lane];
    const float s0 = sinT[s * HD_ + lane];
    const float c1 = cosT[s * HD_ + lane + 32];
    const float s1 = sinT[s * HD_ + lane + 32];

    row[lane]      = n0 * c0 - n1 * s0;
    row[lane + 32] = n1 * c1 + n0 * s1;
}

// ---------------------------------------------------------------------------
// One-shot K/V split-bf16 conversion (numerics identical to in-loop splitpack)
// ---------------------------------------------------------------------------
__global__ void __launch_bounds__(256) convert_kv(const float* __restrict__ k,
                                                  const float* __restrict__ v,
                                                  __nv_bfloat16* __restrict__ khi,
                                                  __nv_bfloat16* __restrict__ klo,
                                                  __nv_bfloat16* __restrict__ vhi,
                                                  __nv_bfloat16* __restrict__ vlo) {
    const int i = blockIdx.x * blockDim.x + threadIdx.x;   // one float4 each
    if (i >= (int)(KVELEM / 4)) return;
    float4 kk = ((const float4*)k)[i];
    float4 vv = ((const float4*)v)[i];
    uint32_t h0, h1, l0, l1;
    splitpack(kk.x, kk.y, h0, l0);
    splitpack(kk.z, kk.w, h1, l1);
    ((uint2*)khi)[i] = make_uint2(h0, h1);
    ((uint2*)klo)[i] = make_uint2(l0, l1);
    splitpack(vv.x, vv.y, h0, l0);
    splitpack(vv.z, vv.w, h1, l1);
    ((uint2*)vhi)[i] = make_uint2(h0, h1);
    ((uint2*)vlo)[i] = make_uint2(l0, l1);
}

// ---------------------------------------------------------------------------
// Tensor-core causal flash attention, split-bf16, pre-converted K/V.
// CTA: 64 q rows (4 warps x m16), 128 threads (R11 shape), key tiles of 32.
// ---------------------------------------------------------------------------
#define KVST 72

__global__ void __launch_bounds__(128) attn_tc(const float* __restrict__ q,
                                               const __nv_bfloat16* __restrict__ khi,
                                               const __nv_bfloat16* __restrict__ klo,
                                               const __nv_bfloat16* __restrict__ vhi,
                                               const __nv_bfloat16* __restrict__ vlo,
                                               float* __restrict__ o) {
    __shared__ unsigned short ksh_hi[32][KVST], ksh_lo[32][KVST];
    __shared__ unsigned short vsh_hi[32][KVST], vsh_lo[32][KVST];

    const int t    = threadIdx.x;
    const int lane = t & 31;
    const int w    = t >> 5;
    const int gid  = lane >> 2;
    const int tig  = lane & 3;
    const int b    = blockIdx.z;
    const int h    = blockIdx.y;
    const int kh   = h >> 2;
    const int qb   = blockIdx.x * 64;
    const int r0   = qb + w * 16 + gid;

    uint32_t qh[4][4], ql[4][4];
    {
        const float* q0 = q + ((size_t)(b * S_ + r0) * H_ + h) * HD_;
        const float* q1 = q0 + (size_t)8 * H_ * HD_;
#pragma unroll
        for (int kc = 0; kc < 4; kc++) {
            const int d0 = kc * 16 + tig * 2;
            float2 x00 = *(const float2*)(q0 + d0);
            float2 x10 = *(const float2*)(q1 + d0);
            float2 x02 = *(const float2*)(q0 + d0 + 8);
            float2 x12 = *(const float2*)(q1 + d0 + 8);
            splitpack(x00.x * 0.125f, x00.y * 0.125f, qh[kc][0], ql[kc][0]);
            splitpack(x10.x * 0.125f, x10.y * 0.125f, qh[kc][1], ql[kc][1]);
            splitpack(x02.x * 0.125f, x02.y * 0.125f, qh[kc][2], ql[kc][2]);
            splitpack(x12.x * 0.125f, x12.y * 0.125f, qh[kc][3], ql[kc][3]);
        }
    }

    float oc[8][4];
#pragma unroll
    for (int nt = 0; nt < 8; nt++)
#pragma unroll
        for (int r = 0; r < 4; r++) oc[nt][r] = 0.f;
    float m0 = -1e30f, m1 = -1e30f, l0 = 0.f, l1 = 0.f;

    const uint32_t vhi_base = smem_u32(&vsh_hi[0][0]);
    const uint32_t vlo_base = smem_u32(&vsh_lo[0][0]);
    const int lm_key = lane & 15;
    const int lm_d   = (lane >> 4) * 8;

    for (int n0 = 0; n0 < qb + 64; n0 += 32) {
        // pure-copy tile load: 32 keys x 8 uint4 per array, 128 threads x 2
#pragma unroll
        for (int i = 0; i < 2; i++) {
            const int idx = t + i * 128;
            const int key = idx >> 3;
            const int c   = idx & 7;
            const size_t gb = ((size_t)(b * S_ + n0 + key) * KVH_ + kh) * HD_ + c * 8;
            *(uint4*)&ksh_hi[key][c * 8] = *(const uint4*)(khi + gb);
            *(uint4*)&ksh_lo[key][c * 8] = *(const uint4*)(klo + gb);
            *(uint4*)&vsh_hi[key][c * 8] = *(const uint4*)(vhi + gb);
            *(uint4*)&vsh_lo[key][c * 8] = *(const uint4*)(vlo + gb);
        }
        __syncthreads();

        const bool active = (n0 <= qb + w * 16 + 15);   // warp-uniform
        if (active) {
            float sc[4][4];
#pragma unroll
            for (int j = 0; j < 4; j++)
#pragma unroll
                for (int r = 0; r < 4; r++) sc[j][r] = 0.f;

#pragma unroll
            for (int j = 0; j < 4; j++) {
                const int key = j * 8 + gid;
#pragma unroll
                for (int kc = 0; kc < 4; kc++) {
                    const int d = kc * 16 + tig * 2;
                    uint32_t bh0 = *(const uint32_t*)&ksh_hi[key][d];
                    uint32_t bh1 = *(const uint32_t*)&ksh_hi[key][d + 8];
                    uint32_t bl0 = *(const uint32_t*)&ksh_lo[key][d];
                    uint32_t bl1 = *(const uint32_t*)&ksh_lo[key][d + 8];
                    mma_bf16(sc[j], qh[kc], bh0, bh1);
                    mma_bf16(sc[j], qh[kc], bl0, bl1);
                    mma_bf16(sc[j], ql[kc], bh0, bh1);
                }
            }

            if (n0 + 31 > qb + w * 16) {
#pragma unroll
                for (int j = 0; j < 4; j++) {
                    const int col = n0 + j * 8 + tig * 2;
                    if (col     > r0)     sc[j][0] = -1e30f;
                    if (col + 1 > r0)     sc[j][1] = -1e30f;
                    if (col     > r0 + 8) sc[j][2] = -1e30f;
                    if (col + 1 > r0 + 8) sc[j][3] = -1e30f;
                }
            }

            float tm0 = -1e30f, tm1 = -1e30f;
#pragma unroll
            for (int j = 0; j < 4; j++) {
                tm0 = fmaxf(tm0, fmaxf(sc[j][0], sc[j][1]));
                tm1 = fmaxf(tm1, fmaxf(sc[j][2], sc[j][3]));
            }
            tm0 = fmaxf(tm0, __shfl_xor_sync(0xffffffffu, tm0, 1));
            tm0 = fmaxf(tm0, __shfl_xor_sync(0xffffffffu, tm0, 2));
            tm1 = fmaxf(tm1, __shfl_xor_sync(0xffffffffu, tm1, 1));
            tm1 = fmaxf(tm1, __shfl_xor_sync(0xffffffffu, tm1, 2));

            const float mn0 = fmaxf(m0, tm0);
            const float mn1 = fmaxf(m1, tm1);
            const float al0 = exp2f((m0 - mn0) * LOG2E);
            const float al1 = exp2f((m1 - mn1) * LOG2E);
            m0 = mn0;  m1 = mn1;
            l0 *= al0; l1 *= al1;
#pragma unroll
            for (int nt = 0; nt < 8; nt++) {
                oc[nt][0] *= al0; oc[nt][1] *= al0;
                oc[nt][2] *= al1; oc[nt][3] *= al1;
            }
#pragma unroll
            for (int j = 0; j < 4; j++) {
                sc[j][0] = exp2f((sc[j][0] - mn0) * LOG2E);
                sc[j][1] = exp2f((sc[j][1] - mn0) * LOG2E);
                sc[j][2] = exp2f((sc[j][2] - mn1) * LOG2E);
                sc[j][3] = exp2f((sc[j][3] - mn1) * LOG2E);
                l0 += sc[j][0] + sc[j][1];
                l1 += sc[j][2] + sc[j][3];
            }

#pragma unroll
            for (int kc2 = 0; kc2 < 2; kc2++) {
                uint32_t pah[4], pal[4];
                splitpack(sc[2 * kc2][0],     sc[2 * kc2][1],     pah[0], pal[0]);
                splitpack(sc[2 * kc2][2],     sc[2 * kc2][3],     pah[1], pal[1]);
                splitpack(sc[2 * kc2 + 1][0], sc[2 * kc2 + 1][1], pah[2], pal[2]);
                splitpack(sc[2 * kc2 + 1][2], sc[2 * kc2 + 1][3], pah[3], pal[3]);
#pragma unroll
                for (int ntp = 0; ntp < 4; ntp++) {
                    const uint32_t off =
                        (uint32_t)(((kc2 * 16 + lm_key) * KVST + ntp * 16 + lm_d) * 2);
                    uint32_t vh[4], vl[4];
                    ldm4t(vh, vhi_base + off);
                    ldm4t(vl, vlo_base + off);
                    mma_bf16(oc[2 * ntp],     pah, vh[0], vh[1]);
                    mma_bf16(oc[2 * ntp],     pah, vl[0], vl[1]);
                    mma_bf16(oc[2 * ntp],     pal, vh[0], vh[1]);
                    mma_bf16(oc[2 * ntp + 1], pah, vh[2], vh[3]);
                    mma_bf16(oc[2 * ntp + 1], pah, vl[2], vl[3]);
                    mma_bf16(oc[2 * ntp + 1], pal, vh[2], vh[3]);
                }
            }
        }
        __syncthreads();
    }

    l0 += __shfl_xor_sync(0xffffffffu, l0, 1);
    l0 += __shfl_xor_sync(0xffffffffu, l0, 2);
    l1 += __shfl_xor_sync(0xffffffffu, l1, 1);
    l1 += __shfl_xor_sync(0xffffffffu, l1, 2);
    const float inv0 = 1.f / l0;
    const float inv1 = 1.f / l1;

    float* o0 = o + ((size_t)(b * S_ + r0) * H_ + h) * HD_;
    float* o1 = o0 + (size_t)8 * H_ * HD_;
#pragma unroll
    for (int nt = 0; nt < 8; nt++) {
        *(float2*)(o0 + nt * 8 + tig * 2) =
            make_float2(oc[nt][0] * inv0, oc[nt][1] * inv0);
        *(float2*)(o1 + nt * 8 + tig * 2) =
            make_float2(oc[nt][2] * inv1, oc[nt][3] * inv1);
    }
}

// ---------------------------------------------------------------------------
extern "C" void kernel_launch(void* const* d_in, const int* in_sizes, int n_in,
                              void* d_out, int out_size) {
    const float* x     = (const float*)d_in[0];
    // d_in[1] = mask (unused; causal hardcoded)
    const float* cosT  = (const float*)d_in[2];
    const float* sinT  = (const float*)d_in[3];
    const float* Wq    = (const float*)d_in[4];
    const float* Wk    = (const float*)d_in[5];
    const float* Wv    = (const float*)d_in[6];
    const float* Wo    = (const float*)d_in[7];
    const float* wqn   = (const float*)d_in[8];
    const float* wkn   = (const float*)d_in[9];
    float* out = (float*)d_out;

    float *q, *k, *v, *o;
    __nv_bfloat16 *khi, *klo, *vhi, *vlo;
    cudaGetSymbolAddress((void**)&q, g_q);
    cudaGetSymbolAddress((void**)&k, g_k);
    cudaGetSymbolAddress((void**)&v, g_v);
    cudaGetSymbolAddress((void**)&o, g_o);
    cudaGetSymbolAddress((void**)&khi, g_khi);
    cudaGetSymbolAddress((void**)&klo, g_klo);
    cudaGetSymbolAddress((void**)&vhi, g_vhi);
    cudaGetSymbolAddress((void**)&vlo, g_vlo);

    cudaFuncSetAttribute(gemm_tf32,    cudaFuncAttributeMaxDynamicSharedMemorySize, GSMEM);
    cudaFuncSetAttribute(gemm_tf32_kv, cudaFuncAttributeMaxDynamicSharedMemorySize, GSMEM);

    // projections
    gemm_tf32<<<dim3((H_ * HD_) / 128, MROWS / 128), 256, GSMEM>>>(x, Wq, q, H_ * HD_);
    gemm_tf32_kv<<<dim3((KVH_ * HD_) / 128, MROWS / 128, 2), 256, GSMEM>>>(x, Wk, Wv, k, v,
                                                                           KVH_ * HD_);

    // fused RMSNorm + RoPE on q and k
    {
        const int qrows = MROWS * H_;
        const int krows = MROWS * KVH_;
        norm_rope<<<(qrows + 7) / 8, 256>>>(q, wqn, cosT, sinT, H_, qrows);
        norm_rope<<<(krows + 7) / 8, 256>>>(k, wkn, cosT, sinT, KVH_, krows);
    }

    // one-shot K/V split-bf16 conversion
    convert_kv<<<(int)(KVELEM / 4 + 255) / 256, 256>>>(k, v, khi, klo, vhi, vlo);

    // causal GQA attention (split-bf16 tensor cores, pre-converted K/V, R11 shape)
    attn_tc<<<dim3(S_ / 64, H_, B_), 128>>>(q, khi, klo, vhi, vlo, o);

    // output projection
    gemm_tf32<<<dim3(DIN_ / 128, MROWS / 128), 256, GSMEM>>>(o, Wo, out, DIN_);
}